// round 15
// baseline (speedup 1.0000x reference)
#include <cuda_runtime.h>
#include <cuda_fp16.h>
#include <cstdint>

// ---------------- problem constants ----------------
#define NN    50000
#define INF   512
#define HID   128
#define OUTF  40
#define NWX   16      // INF/32 words per row
#define NWH   4       // HID/32 words per row
#define EE    600000
#define NPACKW (NWX*HID + NWH*HID + NWH*OUTF)   // 2720
#define PWB   11      // packw blocks
#define CSNB  250     // colsum blocks (200 rows x 512 cols each)
#define CSPN  1000    // colsum partial rows (250 chunks x 4 row-slices)
#define PACKB (NN/16) // 3125 pack+gemm1 blocks

// ---------------- device scratch ----------------
__device__ __align__(32) float g_csp[CSPN * INF];  // colsum partials (plain stores)
__device__ float    g_cmean[INF];
__device__ float    g_arawp[PWB];
__device__ int      g_wallp[PWB];
__device__ float    g_alpha[3];         // mean(|w|) per layer
__device__ int      g_wall[3];          // 1 if ALL weight bits valid
__device__ __align__(16) unsigned g_w0s[NWX * HID];
__device__ __align__(16) unsigned g_w0v[NWX * HID];
__device__ __align__(16) unsigned g_w1s[NWH * HID];
__device__ __align__(16) unsigned g_w1v[NWH * HID];
__device__ __align__(16) unsigned g_w2s[NWH * OUTF];
__device__ __align__(16) unsigned g_w2v[NWH * OUTF];
__device__ int      g_count[NN];        // starts 0; count adds, scatter restores to 0
__device__ int      g_rowptr[NN + 1];
__device__ int      g_bsum[64];
__device__ float    g_dinv[NN];
__device__ __align__(128) int2    g_adj[EE];       // {src, w_bits}
__device__ __align__(128) __half2 g_hk[NN * 64];   // layer0 GEMM out (exact ints in fp16)
__device__ __align__(128) __half2 g_hkB[NN * 64];  // layer1 GEMM out
__device__ __align__(128) __half2 g_h3k[NN * 20];
__device__ int      g_is64;

// ---------------- 256-bit L2 eviction-priority loads (sm_103a: v8.b32 required) ----------------
__device__ __forceinline__ void ldg_el8(const float* p, float v[8]) {  // keep in L2
    unsigned r0, r1, r2, r3, r4, r5, r6, r7;
    asm volatile("ld.global.nc.L2::evict_last.v8.b32 {%0,%1,%2,%3,%4,%5,%6,%7}, [%8];"
                 : "=r"(r0), "=r"(r1), "=r"(r2), "=r"(r3),
                   "=r"(r4), "=r"(r5), "=r"(r6), "=r"(r7) : "l"(p));
    v[0] = __uint_as_float(r0); v[1] = __uint_as_float(r1);
    v[2] = __uint_as_float(r2); v[3] = __uint_as_float(r3);
    v[4] = __uint_as_float(r4); v[5] = __uint_as_float(r5);
    v[6] = __uint_as_float(r6); v[7] = __uint_as_float(r7);
}
__device__ __forceinline__ void ldg_ef8(const float* p, float v[8]) {  // last use
    unsigned r0, r1, r2, r3, r4, r5, r6, r7;
    asm volatile("ld.global.nc.L2::evict_first.v8.b32 {%0,%1,%2,%3,%4,%5,%6,%7}, [%8];"
                 : "=r"(r0), "=r"(r1), "=r"(r2), "=r"(r3),
                   "=r"(r4), "=r"(r5), "=r"(r6), "=r"(r7) : "l"(p));
    v[0] = __uint_as_float(r0); v[1] = __uint_as_float(r1);
    v[2] = __uint_as_float(r2); v[3] = __uint_as_float(r3);
    v[4] = __uint_as_float(r4); v[5] = __uint_as_float(r5);
    v[6] = __uint_as_float(r6); v[7] = __uint_as_float(r7);
}

// ---------------- threefry2x32 (jax-compatible) ----------------
__device__ __forceinline__ void tf2x32_d(unsigned k0, unsigned k1, unsigned c0, unsigned c1,
                                         unsigned& o0, unsigned& o1) {
    unsigned ks2 = k0 ^ k1 ^ 0x1BD11BDAu;
    unsigned x0 = c0 + k0, x1 = c1 + k1;
#define TFR_(r) { x0 += x1; x1 = __funnelshift_l(x1, x1, r); x1 ^= x0; }
    TFR_(13) TFR_(15) TFR_(26) TFR_(6)  x0 += k1;  x1 += ks2 + 1u;
    TFR_(17) TFR_(29) TFR_(16) TFR_(24) x0 += ks2; x1 += k0 + 2u;
    TFR_(13) TFR_(15) TFR_(26) TFR_(6)  x0 += k0;  x1 += k1 + 3u;
    TFR_(17) TFR_(29) TFR_(16) TFR_(24) x0 += k1;  x1 += ks2 + 4u;
    TFR_(13) TFR_(15) TFR_(26) TFR_(6)  x0 += ks2; x1 += k0 + 5u;
#undef TFR_
    o0 = x0; o1 = x1;
}

static void tf2x32_h(unsigned k0, unsigned k1, unsigned c0, unsigned c1,
                     unsigned& o0, unsigned& o1) {
    unsigned ks2 = k0 ^ k1 ^ 0x1BD11BDAu;
    unsigned x0 = c0 + k0, x1 = c1 + k1;
#define TFRH(r) { x0 += x1; x1 = (x1 << r) | (x1 >> (32 - r)); x1 ^= x0; }
    TFRH(13) TFRH(15) TFRH(26) TFRH(6)  x0 += k1;  x1 += ks2 + 1u;
    TFRH(17) TFRH(29) TFRH(16) TFRH(24) x0 += ks2; x1 += k0 + 2u;
    TFRH(13) TFRH(15) TFRH(26) TFRH(6)  x0 += k0;  x1 += k1 + 3u;
    TFRH(17) TFRH(29) TFRH(16) TFRH(24) x0 += k1;  x1 += ks2 + 4u;
    TFRH(13) TFRH(15) TFRH(26) TFRH(6)  x0 += ks2; x1 += k0 + 5u;
#undef TFRH
    o0 = x0; o1 = x1;
}

__device__ __forceinline__ int detect64(const unsigned* eb) {
    int ok = 1;
    for (int t = 0; t < 64; t++) if (eb[2 * t + 1] != 0u) { ok = 0; break; }
    return ok;
}

// ---------------- k_pre: degree count | packw | colsum LAST (x pinned in L2) ----------------
__global__ void __launch_bounds__(256) k_pre(const float* __restrict__ x,
                      const float* __restrict__ w0, const float* __restrict__ w1,
                      const float* __restrict__ w2,
                      const void* __restrict__ ei, int E) {
    int b = blockIdx.x, tid = threadIdx.x;
    int cntb = (E + 255) / 256;
    if (b < cntb) {                      // ---- degree count (local is64 detect)
        __shared__ int sis;
        if (tid == 0) sis = detect64((const unsigned*)ei);
        __syncthreads();
        int e = b * 256 + tid;
        if (e < E) {
            int dst = sis ? (int)((const long long*)ei)[e] : ((const int*)ei)[e];
            atomicAdd(&g_count[dst], 1);
        }
    } else if (b < cntb + PWB) {         // ---- packw
        __shared__ float sha[8];
        __shared__ int   shok;
        if (tid == 0) shok = 1;
        __syncthreads();
        int t = (b - cntb) * 256 + tid;
        bool valid = (t < NPACKW);
        const float* src = w0; int stride = HID, w = 0, j = 0;
        unsigned *ds = g_w0s, *dv = g_w0v;
        if (valid) {
            if (t < NWX * HID) {
                w = t >> 7; j = t & 127;
            } else if (t < NWX * HID + NWH * HID) {
                int u = t - NWX * HID;
                w = u >> 7; j = u & 127; src = w1; ds = g_w1s; dv = g_w1v;
            } else {
                int u = t - NWX * HID - NWH * HID;
                w = u / OUTF; j = u % OUTF; src = w2; stride = OUTF; ds = g_w2s; dv = g_w2v;
            }
        }
        unsigned sb = 0, vb = 0;
        float asum = 0.0f;
        if (valid) {
#pragma unroll 8
            for (int i = 0; i < 32; i++) {
                float v = __ldg(&src[(w * 32 + i) * stride + j]);
                sb |= (v > 0.0f ? 1u : 0u) << i;
                vb |= (v != 0.0f ? 1u : 0u) << i;
                asum += fabsf(v);
            }
            ds[w * stride + j] = sb;
            dv[w * stride + j] = vb;
            if (vb != 0xffffffffu) atomicAnd(&shok, 0);
        }
        for (int off = 16; off; off >>= 1) asum += __shfl_xor_sync(0xffffffffu, asum, off);
        if ((tid & 31) == 0) sha[tid >> 5] = asum;
        __syncthreads();
        if (tid == 0) {
            float s = 0.0f;
            for (int i = 0; i < 8; i++) s += sha[i];
            g_arawp[b - cntb] = s;
            g_wallp[b - cntb] = shok;
        }
    } else {                             // ---- colsum: 200 rows x 512 cols per block (v8 loads)
        int cb = b - cntb - PWB;         // 0..249
        int cg = tid & 63, rs = tid >> 6;    // col-group (8 cols), row-slice (50 rows)
        int r0 = cb * 200 + rs * 50;
        const float* base = x + (size_t)r0 * INF + cg * 8;
        float s[8] = {0, 0, 0, 0, 0, 0, 0, 0};
        for (int r = 0; r < 50; r++) {
            float v[8];
            ldg_el8(base + (size_t)r * INF, v);   // pin x in L2
#pragma unroll
            for (int k = 0; k < 8; k++) s[k] += v[k];
        }
        float* dst = &g_csp[(size_t)(cb * 4 + rs) * INF + cg * 8];
#pragma unroll
        for (int k = 0; k < 8; k++) dst[k] = s[k];
    }
}

// ---------------- k_scanA: block sums + dinv | colmean x2 | alpha/wall | is64 ----------------
__global__ void __launch_bounds__(1024) k_scanA(const void* __restrict__ ei) {
    int b = blockIdx.x;
    if (b < 49) {
        int i = b * 1024 + threadIdx.x;
        int v = (i < NN) ? g_count[i] : 0;
        if (i < NN) g_dinv[i] = rsqrtf((float)(v + 1));
        int s = v;
        for (int off = 16; off; off >>= 1) s += __shfl_xor_sync(0xffffffffu, s, off);
        __shared__ int sh[32];
        int l = threadIdx.x & 31, w = threadIdx.x >> 5;
        if (l == 0) sh[w] = s;
        __syncthreads();
        if (w == 0) {
            s = sh[l];
            for (int off = 16; off; off >>= 1) s += __shfl_xor_sync(0xffffffffu, s, off);
            if (l == 0) g_bsum[b] = s;
        }
    } else if (b < 51) {                 // column means: 2 blocks x 256 cols, 4-way split
        __shared__ float red[4][256];
        int cl = threadIdx.x & 255, g = threadIdx.x >> 8;
        int c = (b - 49) * 256 + cl;
        float s = 0.0f;
        for (int i = g; i < CSPN; i += 4) s += g_csp[(size_t)i * INF + c];
        red[g][cl] = s;
        __syncthreads();
        if (g == 0)
            g_cmean[c] = (red[0][cl] + red[1][cl] + red[2][cl] + red[3][cl])
                         * (1.0f / (float)NN);
    } else if (b == 51) {                // alpha + wall
        if (threadIdx.x == 0) {
            float s0 = 0, s1 = 0, s2 = 0; int k0 = 1, k1 = 1, k2 = 1;
            for (int i = 0; i < 8; i++)  { s0 += g_arawp[i]; k0 &= g_wallp[i]; }
            for (int i = 8; i < 10; i++) { s1 += g_arawp[i]; k1 &= g_wallp[i]; }
            s2 = g_arawp[10]; k2 = g_wallp[10];
            g_alpha[0] = s0 * (1.0f / (float)(INF * HID));
            g_alpha[1] = s1 * (1.0f / (float)(HID * HID));
            g_alpha[2] = s2 * (1.0f / (float)(HID * OUTF));
            g_wall[0] = k0; g_wall[1] = k1; g_wall[2] = k2;
        }
    } else {                             // is64 (for scatter)
        if (threadIdx.x == 0) g_is64 = detect64((const unsigned*)ei);
    }
}

// ---------------- k_scanB: local 49-scan + rowptr ----------------
__global__ void __launch_bounds__(1024) k_scanB() {
    __shared__ int sp[64];
    __shared__ int sh[32];
    int tid = threadIdx.x, l = tid & 31, w = tid >> 5;
    if (w == 0) {                        // warp 0: scan the 49 block sums
        int a0 = g_bsum[l];
        int a1 = (l < 17) ? g_bsum[32 + l] : 0;
        int i0 = a0, i1 = a1;
        for (int off = 1; off < 32; off <<= 1) {
            int t0 = __shfl_up_sync(0xffffffffu, i0, off);
            int t1 = __shfl_up_sync(0xffffffffu, i1, off);
            if (l >= off) { i0 += t0; i1 += t1; }
        }
        int tot0 = __shfl_sync(0xffffffffu, i0, 31);
        sp[l]      = i0 - a0;
        sp[32 + l] = i1 - a1 + tot0;
        int grand = __shfl_sync(0xffffffffu, i1, 16) + tot0;
        if (l == 0 && blockIdx.x == 48) g_rowptr[NN] = grand;
    }
    __syncthreads();
    int base = sp[blockIdx.x];
    int i = blockIdx.x * 1024 + tid;
    int v = (i < NN) ? g_count[i] : 0;
    int x = v;
    for (int off = 1; off < 32; off <<= 1) {
        int t = __shfl_up_sync(0xffffffffu, x, off);
        if (l >= off) x += t;
    }
    if (l == 31) sh[w] = x;
    __syncthreads();
    if (w == 0) {
        int y = sh[l];
        for (int off = 1; off < 32; off <<= 1) {
            int t = __shfl_up_sync(0xffffffffu, y, off);
            if (l >= off) y += t;
        }
        sh[l] = y;
    }
    __syncthreads();
    int excl = x - v + ((w > 0) ? sh[w - 1] : 0);
    if (i < NN) g_rowptr[i] = base + excl;
}

// ---------------- fused: scatter | packX + gemm1 (rows reversed for L2 reuse) ----------------
__global__ void __launch_bounds__(512) k_scpg1(const void* __restrict__ ei, int E, int scb,
                                               const float* __restrict__ x) {
    __shared__ uint2 asv[16][NWX];
    __shared__ int   srt[16];
    __shared__ uint2 ws2[NWX * 64];
    __shared__ uint2 wv2[NWX * 64];
    int b = blockIdx.x, tid = threadIdx.x;
    if (b < scb) {                       // ---- scatter (countdown restores g_count to 0)
        int e = b * 512 + tid;
        if (e < E) {
            int is64 = g_is64;
            int dst, src;
            if (is64) {
                dst = (int)((const long long*)ei)[e];
                src = (int)((const long long*)ei)[(size_t)E + e];
            } else {
                dst = ((const int*)ei)[e];
                src = ((const int*)ei)[E + e];
            }
            int old = atomicSub(&g_count[dst], 1);
            g_adj[g_rowptr[dst] + old - 1] =
                make_int2(src, __float_as_int(g_dinv[dst] * g_dinv[src]));
        }
        return;
    }
    // ---- pack + gemm1
    int wall = g_wall[0];
    {
        unsigned* u = (unsigned*)ws2;
        for (int i = tid; i < NWX * HID; i += 512) u[i] = g_w0s[i];
        if (!wall) {
            unsigned* v = (unsigned*)wv2;
            for (int i = tid; i < NWX * HID; i += 512) v[i] = g_w0v[i];
        }
    }
    int wid = tid >> 5, l = tid & 31;
    int r0 = (PACKB - 1 - (b - scb)) * 16;   // reversed: tail of x is hottest in L2
    int r = r0 + wid;
    int tot = 0;
#pragma unroll
    for (int pass = 0; pass < 2; pass++) {
        int c0 = pass * 256 + 8 * l;
        float xv[8];
        ldg_ef8(&x[(size_t)r * INF + c0], xv);       // last use of x, 256-bit
        float4 cmA = __ldg(&((const float4*)g_cmean)[c0 >> 2]);
        float4 cmB = __ldg(&((const float4*)g_cmean)[(c0 >> 2) + 1]);
        float cm[8] = {cmA.x, cmA.y, cmA.z, cmA.w, cmB.x, cmB.y, cmB.z, cmB.w};
        unsigned sb8 = 0, vb8 = 0;
#pragma unroll
        for (int k = 0; k < 8; k++) {
            float t = xv[k] - cm[k];
            sb8 |= (t > 0.0f ? 1u : 0u) << k;
            vb8 |= (t != 0.0f ? 1u : 0u) << k;
        }
        unsigned sacc = sb8 << (8 * (l & 3));
        unsigned vacc = vb8 << (8 * (l & 3));
        sacc |= __shfl_xor_sync(0xffffffffu, sacc, 1);
        vacc |= __shfl_xor_sync(0xffffffffu, vacc, 1);
        sacc |= __shfl_xor_sync(0xffffffffu, sacc, 2);
        vacc |= __shfl_xor_sync(0xffffffffu, vacc, 2);
        if ((l & 3) == 0) {
            asv[wid][pass * 8 + (l >> 2)] = make_uint2(sacc, vacc);
            tot += __popc(vacc);
        }
    }
    tot += __shfl_xor_sync(0xffffffffu, tot, 4);
    tot += __shfl_xor_sync(0xffffffffu, tot, 8);
    tot += __shfl_xor_sync(0xffffffffu, tot, 16);
    if (l == 0) srt[wid] = tot;
    __syncthreads();
    int tx = tid & 63, ty = tid >> 6;    // rows ty, ty+8; cols 2tx, 2tx+1
    int k00, k01, k10, k11;
    if (wall) {
        int p00 = 0, p01 = 0, p10 = 0, p11 = 0;
#pragma unroll
        for (int w = 0; w < NWX; w++) {
            uint2 aA = asv[ty][w], aB = asv[ty + 8][w];
            uint2 bb = ws2[w * 64 + tx];
            p00 += __popc(aA.y & ~(aA.x ^ bb.x));
            p01 += __popc(aA.y & ~(aA.x ^ bb.y));
            p10 += __popc(aB.y & ~(aB.x ^ bb.x));
            p11 += __popc(aB.y & ~(aB.x ^ bb.y));
        }
        int ra = srt[ty], rb = srt[ty + 8];
        k00 = 2 * p00 - ra; k01 = 2 * p01 - ra;
        k10 = 2 * p10 - rb; k11 = 2 * p11 - rb;
    } else {
        int p00 = 0, t00 = 0, p01 = 0, t01 = 0, p10 = 0, t10 = 0, p11 = 0, t11 = 0;
#pragma unroll
        for (int w = 0; w < NWX; w++) {
            uint2 aA = asv[ty][w], aB = asv[ty + 8][w];
            uint2 bb = ws2[w * 64 + tx];
            uint2 vv = wv2[w * 64 + tx];
            unsigned mA0 = aA.y & vv.x, mA1 = aA.y & vv.y;
            unsigned mB0 = aB.y & vv.x, mB1 = aB.y & vv.y;
            p00 += __popc(mA0 & ~(aA.x ^ bb.x)); t00 += __popc(mA0);
            p01 += __popc(mA1 & ~(aA.x ^ bb.y)); t01 += __popc(mA1);
            p10 += __popc(mB0 & ~(aB.x ^ bb.x)); t10 += __popc(mB0);
            p11 += __popc(mB1 & ~(aB.x ^ bb.y)); t11 += __popc(mB1);
        }
        k00 = 2 * p00 - t00; k01 = 2 * p01 - t01;
        k10 = 2 * p10 - t10; k11 = 2 * p11 - t11;
    }
    g_hk[(r0 + ty) * 64 + tx]     = __floats2half2_rn((float)k00, (float)k01);
    g_hk[(r0 + ty + 8) * 64 + tx] = __floats2half2_rn((float)k10, (float)k11);
}

// ---------------- fused: aggregate + bias + dropout + pack + next GEMM ----------------
__global__ void __launch_bounds__(256) k_agg_gemm(const float* __restrict__ bias, int layer,
                                                  unsigned fk0, unsigned fk1) {
    __shared__ uint2 ssv[8][NWH];
    __shared__ int   srt[8];
    __shared__ uint2 ws2[NWH * 64];
    __shared__ uint2 wv2[NWH * 64];
    int tid = threadIdx.x, wid = tid >> 5, l = tid & 31;
    int wall = g_wall[layer + 1];
    {
        const unsigned* wsrc = (layer == 0) ? g_w1s : g_w2s;
        const unsigned* wvsrc = (layer == 0) ? g_w1v : g_w2v;
        int nw = (layer == 0) ? NWH * HID : NWH * OUTF;
        if (tid < nw) {
            ((unsigned*)ws2)[tid] = wsrc[tid];
            if (!wall) ((unsigned*)wv2)[tid] = wvsrc[tid];
        }
        if (layer == 0 && tid + 256 < nw) {
            ((unsigned*)ws2)[tid + 256] = wsrc[tid + 256];
            if (!wall) ((unsigned*)wv2)[tid + 256] = wvsrc[tid + 256];
        }
    }
    int r = blockIdx.x * 8 + wid;
    float dr = g_dinv[r];
    float sw = dr * dr;
    const uint2* hrow = (const uint2*)((layer == 0) ? g_hk : g_hkB);
    uint2 hv = __ldg(&hrow[r * 32 + l]);
    float2 f01 = __half22float2(*(__half2*)&hv.x);
    float2 f23 = __half22float2(*(__half2*)&hv.y);
    float a0 = sw * f01.x, a1 = sw * f01.y;
    float a2 = sw * f23.x, a3 = sw * f23.y;
    int p = g_rowptr[r], pe = g_rowptr[r + 1];
    while (p + 2 <= pe) {                // unroll-2: batch 4 loads for MLP
        int2 e0 = __ldg(&g_adj[p]);
        int2 e1 = __ldg(&g_adj[p + 1]);
        uint2 v0 = __ldg(&hrow[e0.x * 32 + l]);
        uint2 v1 = __ldg(&hrow[e1.x * 32 + l]);
        float w0 = __int_as_float(e0.y);
        float w1 = __int_as_float(e1.y);
        float2 u01 = __half22float2(*(__half2*)&v0.x);
        float2 u23 = __half22float2(*(__half2*)&v0.y);
        a0 += w0 * u01.x; a1 += w0 * u01.y;
        a2 += w0 * u23.x; a3 += w0 * u23.y;
        u01 = __half22float2(*(__half2*)&v1.x);
        u23 = __half22float2(*(__half2*)&v1.y);
        a0 += w1 * u01.x; a1 += w1 * u01.y;
        a2 += w1 * u23.x; a3 += w1 * u23.y;
        p += 2;
    }
    if (p < pe) {
        int2 e0 = __ldg(&g_adj[p]);
        uint2 v0 = __ldg(&hrow[e0.x * 32 + l]);
        float w0 = __int_as_float(e0.y);
        float2 u01 = __half22float2(*(__half2*)&v0.x);
        float2 u23 = __half22float2(*(__half2*)&v0.y);
        a0 += w0 * u01.x; a1 += w0 * u01.y;
        a2 += w0 * u23.x; a3 += w0 * u23.y;
    }
    float alpha = g_alpha[layer];
    float4 b4 = __ldg(&((const float4*)bias)[l]);
    float vv[4];
    vv[0] = alpha * a0 + b4.x;
    vv[1] = alpha * a1 + b4.y;
    vv[2] = alpha * a2 + b4.z;
    vv[3] = alpha * a3 + b4.w;
    unsigned base = (unsigned)(r * HID + 4 * l);
    unsigned sn = 0, vn = 0;
#pragma unroll
    for (int k = 0; k < 4; k++) {
        unsigned o0, o1;
        tf2x32_d(fk0, fk1, 0u, base + (unsigned)k, o0, o1);
        unsigned bits = o0 ^ o1;                    // jax partitionable path
        bool keep = ((int)bits >= 0);               // uniform < 0.5
        if (vv[k] > 0.0f) sn |= 1u << k;
        if (keep && vv[k] != 0.0f) vn |= 1u << k;
    }
    int sh = 4 * (l & 7);
    unsigned s4 = sn << sh, v4 = vn << sh;
    s4 |= __shfl_xor_sync(0xffffffffu, s4, 1);  v4 |= __shfl_xor_sync(0xffffffffu, v4, 1);
    s4 |= __shfl_xor_sync(0xffffffffu, s4, 2);  v4 |= __shfl_xor_sync(0xffffffffu, v4, 2);
    s4 |= __shfl_xor_sync(0xffffffffu, s4, 4);  v4 |= __shfl_xor_sync(0xffffffffu, v4, 4);
    int t = ((l & 7) == 0) ? __popc(v4) : 0;
    t += __shfl_xor_sync(0xffffffffu, t, 8);
    t += __shfl_xor_sync(0xffffffffu, t, 16);
    if ((l & 7) == 0) ssv[wid][l >> 3] = make_uint2(s4, v4);
    if (l == 0) srt[wid] = t;
    __syncthreads();
    // ---- in-block GEMM over the 8 freshly packed rows
    if (layer == 0) {                    // 8 rows x 128 cols -> g_hkB
        int tx = tid & 63, ty = tid >> 6;   // rows ty, ty+4
        int k00, k01, k10, k11;
        if (wall) {
            int p00 = 0, p01 = 0, p10 = 0, p11 = 0;
#pragma unroll
            for (int w = 0; w < NWH; w++) {
                uint2 aA = ssv[ty][w], aB = ssv[ty + 4][w];
                uint2 bb = ws2[w * 64 + tx];
                p00 += __popc(aA.y & ~(aA.x ^ bb.x));
                p01 += __popc(aA.y & ~(aA.x ^ bb.y));
                p10 += __popc(aB.y & ~(aB.x ^ bb.x));
                p11 += __popc(aB.y & ~(aB.x ^ bb.y));
            }
            int ra = srt[ty], rb = srt[ty + 4];
            k00 = 2 * p00 - ra; k01 = 2 * p01 - ra;
            k10 = 2 * p10 - rb; k11 = 2 * p11 - rb;
        } else {
            int p00 = 0, t00 = 0, p01 = 0, t01 = 0, p10 = 0, t10 = 0, p11 = 0, t11 = 0;
#pragma unroll
            for (int w = 0; w < NWH; w++) {
                uint2 aA = ssv[ty][w], aB = ssv[ty + 4][w];
                uint2 bb = ws2[w * 64 + tx];
                uint2 vm = wv2[w * 64 + tx];
                unsigned mA0 = aA.y & vm.x, mA1 = aA.y & vm.y;
                unsigned mB0 = aB.y & vm.x, mB1 = aB.y & vm.y;
                p00 += __popc(mA0 & ~(aA.x ^ bb.x)); t00 += __popc(mA0);
                p01 += __popc(mA1 & ~(aA.x ^ bb.y)); t01 += __popc(mA1);
                p10 += __popc(mB0 & ~(aB.x ^ bb.x)); t10 += __popc(mB0);
                p11 += __popc(mB1 & ~(aB.x ^ bb.y)); t11 += __popc(mB1);
            }
            k00 = 2 * p00 - t00; k01 = 2 * p01 - t01;
            k10 = 2 * p10 - t10; k11 = 2 * p11 - t11;
        }
        int r0 = blockIdx.x * 8;
        g_hkB[(r0 + ty) * 64 + tx]     = __floats2half2_rn((float)k00, (float)k01);
        g_hkB[(r0 + ty + 4) * 64 + tx] = __floats2half2_rn((float)k10, (float)k11);
    } else {                             // 8 rows x 40 cols -> g_h3k
        if (tid < 160) {
            int ty = tid / 20, tx = tid % 20;  // cols 2tx, 2tx+1
            int k0, k1;
            if (wall) {
                int p0 = 0, p1 = 0;
#pragma unroll
                for (int w = 0; w < NWH; w++) {
                    uint2 a = ssv[ty][w];
                    uint2 bb = ws2[w * 20 + tx];
                    p0 += __popc(a.y & ~(a.x ^ bb.x));
                    p1 += __popc(a.y & ~(a.x ^ bb.y));
                }
                int rt = srt[ty];
                k0 = 2 * p0 - rt; k1 = 2 * p1 - rt;
            } else {
                int p0 = 0, t0 = 0, p1 = 0, t1 = 0;
#pragma unroll
                for (int w = 0; w < NWH; w++) {
                    uint2 a = ssv[ty][w];
                    uint2 bb = ws2[w * 20 + tx];
                    uint2 vm = wv2[w * 20 + tx];
                    unsigned m0 = a.y & vm.x, m1 = a.y & vm.y;
                    p0 += __popc(m0 & ~(a.x ^ bb.x)); t0 += __popc(m0);
                    p1 += __popc(m1 & ~(a.x ^ bb.y)); t1 += __popc(m1);
                }
                k0 = 2 * p0 - t0; k1 = 2 * p1 - t1;
            }
            g_h3k[(blockIdx.x * 8 + ty) * 20 + tx] = __floats2half2_rn((float)k0, (float)k1);
        }
    }
}

// ---------------- final aggregate + bias + log_softmax ----------------
__global__ void __launch_bounds__(256) k_agg_final(const float* __restrict__ bias,
                                                   float* __restrict__ out) {
    int wid = threadIdx.x >> 5, l = threadIdx.x & 31;
    int r = blockIdx.x * 8 + wid;
    float dr = g_dinv[r];
    float sw = dr * dr;
    bool act = (l < 20);
    float a0 = 0.0f, a1 = 0.0f;
    if (act) {
        float2 f = __half22float2(__ldg(&g_h3k[r * 20 + l]));
        a0 = sw * f.x; a1 = sw * f.y;
    }
    int p = g_rowptr[r], pe = g_rowptr[r + 1];
    while (p + 2 <= pe) {
        int2 e0 = __ldg(&g_adj[p]);
        int2 e1 = __ldg(&g_adj[p + 1]);
        __half2 u0 = act ? __ldg(&g_h3k[e0.x * 20 + l]) : __half2();
        __half2 u1 = act ? __ldg(&g_h3k[e1.x * 20 + l]) : __half2();
        float w0 = __int_as_float(e0.y);
        float w1 = __int_as_float(e1.y);
        float2 f0 = __half22float2(u0);
        float2 f1 = __half22float2(u1);
        a0 += w0 * f0.x; a1 += w0 * f0.y;
        a0 += w1 * f1.x; a1 += w1 * f1.y;
        p += 2;
    }
    if (p < pe) {
        int2 e0 = __ldg(&g_adj[p]);
        __half2 u0 = act ? __ldg(&g_h3k[e0.x * 20 + l]) : __half2();
        float w0 = __int_as_float(e0.y);
        float2 f0 = __half22float2(u0);
        a0 += w0 * f0.x; a1 += w0 * f0.y;
    }
    float alpha = g_alpha[2];
    float v0 = 0.0f, v1 = 0.0f;
    if (act) {
        float2 b2v = __ldg(&((const float2*)bias)[l]);
        v0 = alpha * a0 + b2v.x;
        v1 = alpha * a1 + b2v.y;
    }
    float m = act ? fmaxf(v0, v1) : -3.4e38f;
    for (int off = 16; off; off >>= 1) m = fmaxf(m, __shfl_xor_sync(0xffffffffu, m, off));
    float s = act ? (expf(v0 - m) + expf(v1 - m)) : 0.0f;
    for (int off = 16; off; off >>= 1) s += __shfl_xor_sync(0xffffffffu, s, off);
    float lse = m + logf(s);
    if (act) {
        float2 o; o.x = v0 - lse; o.y = v1 - lse;
        ((float2*)out)[r * 20 + l] = o;
    }
}

// ---------------- launch ----------------
extern "C" void kernel_launch(void* const* d_in, const int* in_sizes, int n_in,
                              void* d_out, int out_size) {
    const float* x  = (const float*)d_in[0];
    const void*  ei = d_in[1];
    const float* w0 = (const float*)d_in[2];
    const float* b0 = (const float*)d_in[3];
    const float* w1 = (const float*)d_in[4];
    const float* b1 = (const float*)d_in[5];
    const float* w2 = (const float*)d_in[6];
    const float* b2 = (const float*)d_in[7];
    float* out = (float*)d_out;
    int E = in_sizes[1] / 2;

    // dropout fold-in keys: fold_in(key(42), i) = threefry((0,42), (0,i))
    unsigned fk[2][2];
    for (int i = 0; i < 2; i++) tf2x32_h(0u, 42u, 0u, (unsigned)i, fk[i][0], fk[i][1]);

    int cntb = (E + 255) / 256;
    k_pre<<<cntb + PWB + CSNB, 256>>>(x, w0, w1, w2, ei, E);
    k_scanA<<<53, 1024>>>(ei);
    k_scanB<<<49, 1024>>>();
    int scb = (E + 511) / 512;
    k_scpg1<<<scb + PACKB, 512>>>(ei, E, scb, x);
    k_agg_gemm<<<NN / 8, 256>>>(b0, 0, fk[0][0], fk[0][1]);
    k_agg_gemm<<<NN / 8, 256>>>(b1, 1, fk[1][0], fk[1][1]);
    k_agg_final<<<NN / 8, 256>>>(b2, out);
}